// round 7
// baseline (speedup 1.0000x reference)
#include <cuda_runtime.h>
#include <cuda_bf16.h>
#include <cstdint>

// RBFN: out[n] = b + sum_c W_c * exp(-sigma_c^2 * max(||x_n||^2 + ||c_c||^2 - 2 x_n.c_c, 0))
// N=131072, D=64, C=512.  ldmatrix + mma.sync.m16n8k16 bf16/f32 (plain sm_103 ISA).
//
// R4 -> R5: epilogue = cheap screen (exp underflows ~everywhere). Rare hits go
// through shared atomicAdd into a single part[128]; no shfl-reduce, no 16x128
// partial matrix. MMA reordered k-outer for 4 independent chains.

#define NROWS   131072
#define DDIM    64
#define CDIM    512
#define M_TILE  128
#define NTILES  (NROWS / M_TILE)   // 1024
#define GRID    148
#define NTHREADS 512
#define NWARPS  16

#define ROW_BYTES 128   // 64 bf16 per row

// smem layout (dynamic base is 1024-aligned)
#define SMEM_B     0                        // 512 * 128B = 65536
#define SMEM_A     (SMEM_B + 65536)         // 2 buffers * 16384
#define SMEM_KK    (SMEM_A + 2*16384)       // float2[512] = 4096
#define SMEM_WS    (SMEM_KK + 4096)         // float[512]  = 2048
#define SMEM_X2    (SMEM_WS + 2048)         // 2 * float[128] = 1024
#define SMEM_PART  (SMEM_X2 + 1024)         // float[128] = 512
#define SMEM_TOTAL (SMEM_PART + 512 + 128)

static __device__ __forceinline__ uint32_t smem_u32(const void* p) {
    uint32_t a;
    asm("{ .reg .u64 t; cvta.to.shared.u64 t, %1; cvt.u32.u64 %0, t; }" : "=r"(a) : "l"(p));
    return a;
}
static __device__ __forceinline__ uint32_t swz(uint32_t off) {
    return off ^ ((off >> 3) & 0x70);
}
static __device__ __forceinline__ uint32_t pack2(float a, float b) {
    __nv_bfloat162 h = __floats2bfloat162_rn(a, b);
    return *reinterpret_cast<uint32_t*>(&h);
}
static __device__ __forceinline__ float ex2f(float e) {
    float r; asm("ex2.approx.ftz.f32 %0, %1;" : "=f"(r) : "f"(e)); return r;
}
static __device__ __forceinline__ uint32_t lds32(uint32_t addr) {
    uint32_t v; asm volatile("ld.shared.b32 %0, [%1];" : "=r"(v) : "r"(addr)); return v;
}

#define STS128(addr, v) \
    asm volatile("st.shared.v4.b32 [%0], {%1,%2,%3,%4};" :: "r"(addr), "r"((v).x), "r"((v).y), "r"((v).z), "r"((v).w) : "memory")

#define LDMATRIX_X4(r0, r1, r2, r3, addr) \
    asm volatile("ldmatrix.sync.aligned.m8n8.x4.shared.b16 {%0,%1,%2,%3}, [%4];" \
        : "=r"(r0), "=r"(r1), "=r"(r2), "=r"(r3) : "r"(addr))

#define MMA16816(c0, c1, c2, c3, a0, a1, a2, a3, b0, b1) \
    asm volatile("mma.sync.aligned.m16n8k16.row.col.f32.bf16.bf16.f32 " \
        "{%0,%1,%2,%3}, {%4,%5,%6,%7}, {%8,%9}, {%0,%1,%2,%3};" \
        : "+f"(c0), "+f"(c1), "+f"(c2), "+f"(c3) \
        : "r"(a0), "r"(a1), "r"(a2), "r"(a3), "r"(b0), "r"(b1))

__global__ void __launch_bounds__(NTHREADS, 1)
rbfn_kernel(const float* __restrict__ x,
            const float* __restrict__ centres,
            const float* __restrict__ sigmas,
            const float* __restrict__ W,
            const float* __restrict__ bptr,
            float* __restrict__ out)
{
    extern __shared__ char smem[];
    const uint32_t sbase = smem_u32(smem);
    const int tid = threadIdx.x;
    const int wid = tid >> 5;
    const int lid = tid & 31;

    const float LOG2E = 1.4426950408889634f;
    float2* kk12 = reinterpret_cast<float2*>(smem + SMEM_KK);
    float*  wcs  = reinterpret_cast<float*>(smem + SMEM_WS);
    float*  x2s  = reinterpret_cast<float*>(smem + SMEM_X2);   // [2][128]
    float*  part = reinterpret_cast<float*>(smem + SMEM_PART); // [128]

    // ---- one-time: centres -> bf16 SW128 smem, per-centre constants ----
    for (int c = tid; c < CDIM; c += NTHREADS) {
        const float4* cr = reinterpret_cast<const float4*>(centres + c * DDIM);
        float c2 = 0.f;
#pragma unroll
        for (int j = 0; j < 8; j++) {
            float4 v0 = cr[2 * j];
            float4 v1 = cr[2 * j + 1];
            c2 += v0.x * v0.x + v0.y * v0.y + v0.z * v0.z + v0.w * v0.w
                + v1.x * v1.x + v1.y * v1.y + v1.z * v1.z + v1.w * v1.w;
            uint4 pk;
            pk.x = pack2(v0.x, v0.y); pk.y = pack2(v0.z, v0.w);
            pk.z = pack2(v1.x, v1.y); pk.w = pack2(v1.z, v1.w);
            STS128(sbase + SMEM_B + swz((uint32_t)(c * ROW_BYTES + j * 16)), pk);
        }
        float s = sigmas[c];
        float s2 = s * s;
        kk12[c] = make_float2(2.f * s2 * LOG2E, -s2 * c2 * LOG2E);
        wcs[c] = W[c];
    }
    if (tid < M_TILE) part[tid] = 0.f;
    __syncthreads();

    // ---- one-time: B fragments -> registers (warp owns cols wid*32..+31) ----
    uint32_t breg[4][4][2];
#pragma unroll
    for (int nf = 0; nf < 4; nf++) {
#pragma unroll
        for (int k = 0; k < 4; k++) {
            int c = wid * 32 + nf * 8 + (lid >> 2);
            uint32_t byte0 = (uint32_t)(c * ROW_BYTES) + (uint32_t)((k * 16 + (lid & 3) * 2) * 2);
            breg[nf][k][0] = lds32(sbase + SMEM_B + swz(byte0));
            breg[nf][k][1] = lds32(sbase + SMEM_B + swz(byte0 + 16));
        }
    }

    // ---- one-time: per-lane column constants -> registers ----
    float k1v[4][2], kkv[4][2], wv[4][2];
#pragma unroll
    for (int nf = 0; nf < 4; nf++) {
#pragma unroll
        for (int j = 0; j < 2; j++) {
            int c = wid * 32 + nf * 8 + (lid & 3) * 2 + j;
            float2 kv = kk12[c];
            k1v[nf][j] = kv.x;
            kkv[nf][j] = kv.y;
            wv[nf][j]  = wcs[c];
        }
    }
    const float bval = *bptr;

    // ---- prologue: load first tile into buffer 0 ----
    int tile = blockIdx.x;
    if (tid < M_TILE && tile < NTILES) {
        const float4* xr = reinterpret_cast<const float4*>(x + (size_t)(tile * M_TILE + tid) * DDIM);
        float x2 = 0.f;
#pragma unroll
        for (int j = 0; j < 8; j++) {
            float4 v0 = xr[2 * j];
            float4 v1 = xr[2 * j + 1];
            x2 += v0.x * v0.x + v0.y * v0.y + v0.z * v0.z + v0.w * v0.w
                + v1.x * v1.x + v1.y * v1.y + v1.z * v1.z + v1.w * v1.w;
            uint4 pk;
            pk.x = pack2(v0.x, v0.y); pk.y = pack2(v0.z, v0.w);
            pk.z = pack2(v1.x, v1.y); pk.w = pack2(v1.z, v1.w);
            STS128(sbase + SMEM_A + swz((uint32_t)(tid * ROW_BYTES + j * 16)), pk);
        }
        x2s[tid] = x2;
    }
    __syncthreads();

    int p = 0;
    for (; tile < NTILES; tile += GRID) {
        const int row0 = tile * M_TILE;
        const int next = tile + GRID;
        const uint32_t abase = sbase + SMEM_A + (uint32_t)(p * 16384);
        const float* x2cur = x2s + p * M_TILE;

        // ---- prefetch next tile: LDG + pack into registers (overlaps MMA below) ----
        uint4 pf[8];
        float pfx2 = 0.f;
        if (tid < M_TILE && next < NTILES) {
            const float4* xr = reinterpret_cast<const float4*>(x + (size_t)(next * M_TILE + tid) * DDIM);
#pragma unroll
            for (int j = 0; j < 8; j++) {
                float4 v0 = xr[2 * j];
                float4 v1 = xr[2 * j + 1];
                pfx2 += v0.x * v0.x + v0.y * v0.y + v0.z * v0.z + v0.w * v0.w
                      + v1.x * v1.x + v1.y * v1.y + v1.z * v1.z + v1.w * v1.w;
                pf[j].x = pack2(v0.x, v0.y); pf[j].y = pack2(v0.z, v0.w);
                pf[j].z = pack2(v1.x, v1.y); pf[j].w = pack2(v1.z, v1.w);
            }
        }

        // ---- 8 m-fragments of 16 rows; every warp covers all rows, its 32 cols ----
#pragma unroll 1
        for (int mf = 0; mf < 8; mf++) {
            uint32_t a[4][4];
            const uint32_t arow = (uint32_t)(mf * 16 + (lid & 15));
#pragma unroll
            for (int k = 0; k < 4; k++) {
                uint32_t kbyte = (uint32_t)(k * 32 + ((lid >> 4) * 16));
                LDMATRIX_X4(a[k][0], a[k][1], a[k][2], a[k][3],
                            abase + swz(arow * ROW_BYTES + kbyte));
            }

            float acc[4][4];
#pragma unroll
            for (int nf = 0; nf < 4; nf++) {
                acc[nf][0] = 0.f; acc[nf][1] = 0.f; acc[nf][2] = 0.f; acc[nf][3] = 0.f;
            }
            // k-outer: 4 independent HMMA chains between dependent issues
#pragma unroll
            for (int k = 0; k < 4; k++) {
#pragma unroll
                for (int nf = 0; nf < 4; nf++) {
                    MMA16816(acc[nf][0], acc[nf][1], acc[nf][2], acc[nf][3],
                             a[k][0], a[k][1], a[k][2], a[k][3],
                             breg[nf][k][0], breg[nf][k][1]);
                }
            }

            // ---- screen epilogue: exp underflows ~always; hits are rare ----
            const int r0 = mf * 16 + (lid >> 2);
            const int r1 = r0 + 8;
            const float hx20 = 0.5f * x2cur[r0];
            const float hx21 = 0.5f * x2cur[r1];
#pragma unroll
            for (int nf = 0; nf < 4; nf++) {
                float e00 = fmaf(k1v[nf][0], acc[nf][0] - hx20, kkv[nf][0]);
                float e01 = fmaf(k1v[nf][1], acc[nf][1] - hx20, kkv[nf][1]);
                float e10 = fmaf(k1v[nf][0], acc[nf][2] - hx21, kkv[nf][0]);
                float e11 = fmaf(k1v[nf][1], acc[nf][3] - hx21, kkv[nf][1]);
                float m = fmaxf(fmaxf(e00, e01), fmaxf(e10, e11));
                if (m > -126.f) {   // ~never taken
                    if (e00 > -126.f) atomicAdd(part + r0, ex2f(fminf(e00, 0.f)) * wv[nf][0]);
                    if (e01 > -126.f) atomicAdd(part + r0, ex2f(fminf(e01, 0.f)) * wv[nf][1]);
                    if (e10 > -126.f) atomicAdd(part + r1, ex2f(fminf(e10, 0.f)) * wv[nf][0]);
                    if (e11 > -126.f) atomicAdd(part + r1, ex2f(fminf(e11, 0.f)) * wv[nf][1]);
                }
            }
        }

        __syncthreads();   // epilogue atomics done; buf p free

        // final store; re-zero part for next tile; stash prefetched tile
        if (tid < M_TILE) {
            out[row0 + tid] = bval + part[tid];
            part[tid] = 0.f;
            if (next < NTILES) {
                const uint32_t nbase = sbase + SMEM_A + (uint32_t)((p ^ 1) * 16384);
#pragma unroll
                for (int j = 0; j < 8; j++) {
                    STS128(nbase + swz((uint32_t)(tid * ROW_BYTES + j * 16)), pf[j]);
                }
                x2s[(p ^ 1) * M_TILE + tid] = pfx2;
            }
        }
        __syncthreads();   // next buffer + zeroed part visible
        p ^= 1;
    }
}

extern "C" void kernel_launch(void* const* d_in, const int* in_sizes, int n_in,
                              void* d_out, int out_size) {
    const float* x       = (const float*)d_in[0];
    const float* centres = (const float*)d_in[1];
    const float* sigmas  = (const float*)d_in[2];
    const float* W       = (const float*)d_in[3];
    const float* b       = (const float*)d_in[4];
    float* out = (float*)d_out;

    cudaFuncSetAttribute(rbfn_kernel, cudaFuncAttributeMaxDynamicSharedMemorySize, SMEM_TOTAL);
    rbfn_kernel<<<GRID, NTHREADS, SMEM_TOTAL>>>(x, centres, sigmas, W, b, out);
}

// round 10
// speedup vs baseline: 2.5835x; 2.5835x over previous
#include <cuda_runtime.h>
#include <cuda_bf16.h>
#include <cstdint>

// RBFN: out[n] = b + sum_c W_c * exp(-sigma_c^2 * max(||x_n||^2 + ||c_c||^2 - 2 x_n.c_c, 0))
// N=131072, D=64, C=512.  ldmatrix + mma.sync.m16n8k16 bf16/f32 (plain sm_103 ISA).
//
// R5 -> R8: screen threshold -60 (truly never fires: P ~ 4e-10; dropped terms
// <= 2^-60*W, rel err < 1e-15) folded into per-column t_c so the screen is
// 1 FADD + 1 FMNMX per element + one __any_sync-uniform branch per mf.
// Rare path reads k1/kk/W from smem tables; per-column register constants gone.

#define NROWS   131072
#define DDIM    64
#define CDIM    512
#define M_TILE  128
#define NTILES  (NROWS / M_TILE)   // 1024
#define GRID    148
#define NTHREADS 512
#define NWARPS  16

#define ROW_BYTES 128   // 64 bf16 per row

#define SCREEN_T (-60.0f)

// smem layout (dynamic base is 1024-aligned)
#define SMEM_B     0                        // 512 * 128B = 65536
#define SMEM_A     (SMEM_B + 65536)         // 2 buffers * 16384
#define SMEM_KK    (SMEM_A + 2*16384)       // float2[512] = 4096
#define SMEM_WS    (SMEM_KK + 4096)         // float[512]  = 2048
#define SMEM_X2    (SMEM_WS + 2048)         // 2 * float[128] = 1024
#define SMEM_PART  (SMEM_X2 + 1024)         // float[128] = 512
#define SMEM_TOTAL (SMEM_PART + 512 + 128)

static __device__ __forceinline__ uint32_t smem_u32(const void* p) {
    uint32_t a;
    asm("{ .reg .u64 t; cvta.to.shared.u64 t, %1; cvt.u32.u64 %0, t; }" : "=r"(a) : "l"(p));
    return a;
}
static __device__ __forceinline__ uint32_t swz(uint32_t off) {
    return off ^ ((off >> 3) & 0x70);
}
static __device__ __forceinline__ uint32_t pack2(float a, float b) {
    __nv_bfloat162 h = __floats2bfloat162_rn(a, b);
    return *reinterpret_cast<uint32_t*>(&h);
}
static __device__ __forceinline__ float ex2f(float e) {
    float r; asm("ex2.approx.ftz.f32 %0, %1;" : "=f"(r) : "f"(e)); return r;
}
static __device__ __forceinline__ uint32_t lds32(uint32_t addr) {
    uint32_t v; asm volatile("ld.shared.b32 %0, [%1];" : "=r"(v) : "r"(addr)); return v;
}

#define STS128(addr, v) \
    asm volatile("st.shared.v4.b32 [%0], {%1,%2,%3,%4};" :: "r"(addr), "r"((v).x), "r"((v).y), "r"((v).z), "r"((v).w) : "memory")

#define LDMATRIX_X4(r0, r1, r2, r3, addr) \
    asm volatile("ldmatrix.sync.aligned.m8n8.x4.shared.b16 {%0,%1,%2,%3}, [%4];" \
        : "=r"(r0), "=r"(r1), "=r"(r2), "=r"(r3) : "r"(addr))

#define MMA16816(c0, c1, c2, c3, a0, a1, a2, a3, b0, b1) \
    asm volatile("mma.sync.aligned.m16n8k16.row.col.f32.bf16.bf16.f32 " \
        "{%0,%1,%2,%3}, {%4,%5,%6,%7}, {%8,%9}, {%0,%1,%2,%3};" \
        : "+f"(c0), "+f"(c1), "+f"(c2), "+f"(c3) \
        : "r"(a0), "r"(a1), "r"(a2), "r"(a3), "r"(b0), "r"(b1))

__global__ void __launch_bounds__(NTHREADS, 1)
rbfn_kernel(const float* __restrict__ x,
            const float* __restrict__ centres,
            const float* __restrict__ sigmas,
            const float* __restrict__ W,
            const float* __restrict__ bptr,
            float* __restrict__ out)
{
    extern __shared__ char smem[];
    const uint32_t sbase = smem_u32(smem);
    const int tid = threadIdx.x;
    const int wid = tid >> 5;
    const int lid = tid & 31;

    const float LOG2E = 1.4426950408889634f;
    float2* kk12 = reinterpret_cast<float2*>(smem + SMEM_KK);
    float*  wcs  = reinterpret_cast<float*>(smem + SMEM_WS);
    float*  x2s  = reinterpret_cast<float*>(smem + SMEM_X2);   // [2][128]
    float*  part = reinterpret_cast<float*>(smem + SMEM_PART); // [128]

    // ---- one-time: centres -> bf16 SW128 smem, per-centre constants ----
    for (int c = tid; c < CDIM; c += NTHREADS) {
        const float4* cr = reinterpret_cast<const float4*>(centres + c * DDIM);
        float c2 = 0.f;
#pragma unroll
        for (int j = 0; j < 8; j++) {
            float4 v0 = cr[2 * j];
            float4 v1 = cr[2 * j + 1];
            c2 += v0.x * v0.x + v0.y * v0.y + v0.z * v0.z + v0.w * v0.w
                + v1.x * v1.x + v1.y * v1.y + v1.z * v1.z + v1.w * v1.w;
            uint4 pk;
            pk.x = pack2(v0.x, v0.y); pk.y = pack2(v0.z, v0.w);
            pk.z = pack2(v1.x, v1.y); pk.w = pack2(v1.z, v1.w);
            STS128(sbase + SMEM_B + swz((uint32_t)(c * ROW_BYTES + j * 16)), pk);
        }
        float s = sigmas[c];
        float s2 = s * s;
        float k1 = 2.f * s2 * LOG2E;
        float kk = -s2 * c2 * LOG2E;
        kk12[c] = make_float2(k1, kk);
        wcs[c] = W[c];
    }
    if (tid < M_TILE) part[tid] = 0.f;
    __syncthreads();

    // ---- one-time: B fragments -> registers (warp owns cols wid*32..+31) ----
    uint32_t breg[4][4][2];
#pragma unroll
    for (int nf = 0; nf < 4; nf++) {
#pragma unroll
        for (int k = 0; k < 4; k++) {
            int c = wid * 32 + nf * 8 + (lid >> 2);
            uint32_t byte0 = (uint32_t)(c * ROW_BYTES) + (uint32_t)((k * 16 + (lid & 3) * 2) * 2);
            breg[nf][k][0] = lds32(sbase + SMEM_B + swz(byte0));
            breg[nf][k][1] = lds32(sbase + SMEM_B + swz(byte0 + 16));
        }
    }

    // ---- one-time: per-lane screen thresholds t_c = (T - kk)/k1 ----
    // hit condition: e > T  <=>  dot - t_c > 0.5*||x||^2
    float tv[4][2];
#pragma unroll
    for (int nf = 0; nf < 4; nf++) {
#pragma unroll
        for (int j = 0; j < 2; j++) {
            int c = wid * 32 + nf * 8 + (lid & 3) * 2 + j;
            float2 kv = kk12[c];
            tv[nf][j] = (SCREEN_T - kv.y) / kv.x;
        }
    }
    const float bval = *bptr;

    // ---- prologue: load first tile into buffer 0 ----
    int tile = blockIdx.x;
    if (tid < M_TILE && tile < NTILES) {
        const float4* xr = reinterpret_cast<const float4*>(x + (size_t)(tile * M_TILE + tid) * DDIM);
        float x2 = 0.f;
#pragma unroll
        for (int j = 0; j < 8; j++) {
            float4 v0 = xr[2 * j];
            float4 v1 = xr[2 * j + 1];
            x2 += v0.x * v0.x + v0.y * v0.y + v0.z * v0.z + v0.w * v0.w
                + v1.x * v1.x + v1.y * v1.y + v1.z * v1.z + v1.w * v1.w;
            uint4 pk;
            pk.x = pack2(v0.x, v0.y); pk.y = pack2(v0.z, v0.w);
            pk.z = pack2(v1.x, v1.y); pk.w = pack2(v1.z, v1.w);
            STS128(sbase + SMEM_A + swz((uint32_t)(tid * ROW_BYTES + j * 16)), pk);
        }
        x2s[tid] = x2;
    }
    __syncthreads();

    int p = 0;
    for (; tile < NTILES; tile += GRID) {
        const int row0 = tile * M_TILE;
        const int next = tile + GRID;
        const uint32_t abase = sbase + SMEM_A + (uint32_t)(p * 16384);
        const float* x2cur = x2s + p * M_TILE;

        // ---- prefetch next tile: LDG + pack into registers (overlaps MMA below) ----
        uint4 pf[8];
        float pfx2 = 0.f;
        if (tid < M_TILE && next < NTILES) {
            const float4* xr = reinterpret_cast<const float4*>(x + (size_t)(next * M_TILE + tid) * DDIM);
#pragma unroll
            for (int j = 0; j < 8; j++) {
                float4 v0 = xr[2 * j];
                float4 v1 = xr[2 * j + 1];
                pfx2 += v0.x * v0.x + v0.y * v0.y + v0.z * v0.z + v0.w * v0.w
                      + v1.x * v1.x + v1.y * v1.y + v1.z * v1.z + v1.w * v1.w;
                pf[j].x = pack2(v0.x, v0.y); pf[j].y = pack2(v0.z, v0.w);
                pf[j].z = pack2(v1.x, v1.y); pf[j].w = pack2(v1.z, v1.w);
            }
        }

        // ---- 8 m-fragments of 16 rows; every warp covers all rows, its 32 cols ----
#pragma unroll 1
        for (int mf = 0; mf < 8; mf++) {
            uint32_t a[4][4];
            const uint32_t arow = (uint32_t)(mf * 16 + (lid & 15));
#pragma unroll
            for (int k = 0; k < 4; k++) {
                uint32_t kbyte = (uint32_t)(k * 32 + ((lid >> 4) * 16));
                LDMATRIX_X4(a[k][0], a[k][1], a[k][2], a[k][3],
                            abase + swz(arow * ROW_BYTES + kbyte));
            }

            float acc[4][4];
#pragma unroll
            for (int nf = 0; nf < 4; nf++) {
                acc[nf][0] = 0.f; acc[nf][1] = 0.f; acc[nf][2] = 0.f; acc[nf][3] = 0.f;
            }
            // k-outer: 4 independent HMMA chains
#pragma unroll
            for (int k = 0; k < 4; k++) {
#pragma unroll
                for (int nf = 0; nf < 4; nf++) {
                    MMA16816(acc[nf][0], acc[nf][1], acc[nf][2], acc[nf][3],
                             a[k][0], a[k][1], a[k][2], a[k][3],
                             breg[nf][k][0], breg[nf][k][1]);
                }
            }

            // ---- cheap screen: any e > T ?  (dot - t > 0.5*x2) ----
            const int r0 = mf * 16 + (lid >> 2);
            const int r1 = r0 + 8;
            const float hx20 = 0.5f * x2cur[r0];
            const float hx21 = 0.5f * x2cur[r1];
            float m0 = fmaxf(acc[0][0] - tv[0][0], acc[0][1] - tv[0][1]);
            float m1 = fmaxf(acc[0][2] - tv[0][0], acc[0][3] - tv[0][1]);
#pragma unroll
            for (int nf = 1; nf < 4; nf++) {
                m0 = fmaxf(m0, fmaxf(acc[nf][0] - tv[nf][0], acc[nf][1] - tv[nf][1]));
                m1 = fmaxf(m1, fmaxf(acc[nf][2] - tv[nf][0], acc[nf][3] - tv[nf][1]));
            }
            bool hit = fmaxf(m0 - hx20, m1 - hx21) > 0.f;
            if (__any_sync(0xffffffffu, hit)) {   // warp-uniform; ~never taken
#pragma unroll
                for (int nf = 0; nf < 4; nf++) {
#pragma unroll
                    for (int j = 0; j < 2; j++) {
                        int c = wid * 32 + nf * 8 + (lid & 3) * 2 + j;
                        float2 kv = kk12[c];
                        float wc = wcs[c];
                        float e0 = fmaf(kv.x, acc[nf][j]     - hx20, kv.y);
                        float e1 = fmaf(kv.x, acc[nf][2 + j] - hx21, kv.y);
                        if (e0 > SCREEN_T) atomicAdd(part + r0, ex2f(fminf(e0, 0.f)) * wc);
                        if (e1 > SCREEN_T) atomicAdd(part + r1, ex2f(fminf(e1, 0.f)) * wc);
                    }
                }
            }
        }

        __syncthreads();   // epilogue done; buf p free

        // final store; re-zero part; stash prefetched tile
        if (tid < M_TILE) {
            out[row0 + tid] = bval + part[tid];
            part[tid] = 0.f;
            if (next < NTILES) {
                const uint32_t nbase = sbase + SMEM_A + (uint32_t)((p ^ 1) * 16384);
#pragma unroll
                for (int j = 0; j < 8; j++) {
                    STS128(nbase + swz((uint32_t)(tid * ROW_BYTES + j * 16)), pf[j]);
                }
                x2s[(p ^ 1) * M_TILE + tid] = pfx2;
            }
        }
        __syncthreads();   // next buffer + zeroed part visible
        p ^= 1;
    }
}

extern "C" void kernel_launch(void* const* d_in, const int* in_sizes, int n_in,
                              void* d_out, int out_size) {
    const float* x       = (const float*)d_in[0];
    const float* centres = (const float*)d_in[1];
    const float* sigmas  = (const float*)d_in[2];
    const float* W       = (const float*)d_in[3];
    const float* b       = (const float*)d_in[4];
    float* out = (float*)d_out;

    cudaFuncSetAttribute(rbfn_kernel, cudaFuncAttributeMaxDynamicSharedMemorySize, SMEM_TOTAL);
    rbfn_kernel<<<GRID, NTHREADS, SMEM_TOTAL>>>(x, centres, sigmas, W, b, out);
}

// round 11
// speedup vs baseline: 2.7196x; 1.0527x over previous
#include <cuda_runtime.h>
#include <cuda_bf16.h>
#include <cstdint>

// RBFN: out[n] = b + sum_c W_c * exp(-sigma_c^2 * max(||x_n||^2 + ||c_c||^2 - 2 x_n.c_c, 0))
// N=131072, D=64, C=512.  ldmatrix + mma.sync.m16n8k16 bf16/f32 (plain sm_103 ISA).
//
// R8 -> R11: single __syncthreads per tile. part/x2s double-buffered; previous
// tile's output store + part re-zero + next tile's smem stash all overlap the
// current tile's MMA. Prefetch spread over all 512 threads (quarter-rows).

#define NROWS   131072
#define DDIM    64
#define CDIM    512
#define M_TILE  128
#define NTILES  (NROWS / M_TILE)   // 1024
#define GRID    148
#define NTHREADS 512
#define NWARPS  16

#define ROW_BYTES 128   // 64 bf16 per row
#define SCREEN_T (-60.0f)

// smem layout (dynamic base is 1024-aligned)
#define SMEM_B     0                        // 512 * 128B = 65536
#define SMEM_A     (SMEM_B + 65536)         // 2 buffers * 16384
#define SMEM_KK    (SMEM_A + 2*16384)       // float2[512] = 4096
#define SMEM_WS    (SMEM_KK + 4096)         // float[512]  = 2048
#define SMEM_X2    (SMEM_WS + 2048)         // 2 * float[128] = 1024
#define SMEM_PART  (SMEM_X2 + 1024)         // 2 * float[128] = 1024
#define SMEM_TOTAL (SMEM_PART + 1024 + 128)

static __device__ __forceinline__ uint32_t smem_u32(const void* p) {
    uint32_t a;
    asm("{ .reg .u64 t; cvta.to.shared.u64 t, %1; cvt.u32.u64 %0, t; }" : "=r"(a) : "l"(p));
    return a;
}
static __device__ __forceinline__ uint32_t swz(uint32_t off) {
    return off ^ ((off >> 3) & 0x70);
}
static __device__ __forceinline__ uint32_t pack2(float a, float b) {
    __nv_bfloat162 h = __floats2bfloat162_rn(a, b);
    return *reinterpret_cast<uint32_t*>(&h);
}
static __device__ __forceinline__ float ex2f(float e) {
    float r; asm("ex2.approx.ftz.f32 %0, %1;" : "=f"(r) : "f"(e)); return r;
}
static __device__ __forceinline__ uint32_t lds32(uint32_t addr) {
    uint32_t v; asm volatile("ld.shared.b32 %0, [%1];" : "=r"(v) : "r"(addr)); return v;
}

#define STS128(addr, v) \
    asm volatile("st.shared.v4.b32 [%0], {%1,%2,%3,%4};" :: "r"(addr), "r"((v).x), "r"((v).y), "r"((v).z), "r"((v).w) : "memory")

#define LDMATRIX_X4(r0, r1, r2, r3, addr) \
    asm volatile("ldmatrix.sync.aligned.m8n8.x4.shared.b16 {%0,%1,%2,%3}, [%4];" \
        : "=r"(r0), "=r"(r1), "=r"(r2), "=r"(r3) : "r"(addr))

#define MMA16816(c0, c1, c2, c3, a0, a1, a2, a3, b0, b1) \
    asm volatile("mma.sync.aligned.m16n8k16.row.col.f32.bf16.bf16.f32 " \
        "{%0,%1,%2,%3}, {%4,%5,%6,%7}, {%8,%9}, {%0,%1,%2,%3};" \
        : "+f"(c0), "+f"(c1), "+f"(c2), "+f"(c3) \
        : "r"(a0), "r"(a1), "r"(a2), "r"(a3), "r"(b0), "r"(b1))

__global__ void __launch_bounds__(NTHREADS, 1)
rbfn_kernel(const float* __restrict__ x,
            const float* __restrict__ centres,
            const float* __restrict__ sigmas,
            const float* __restrict__ W,
            const float* __restrict__ bptr,
            float* __restrict__ out)
{
    extern __shared__ char smem[];
    const uint32_t sbase = smem_u32(smem);
    const int tid = threadIdx.x;
    const int wid = tid >> 5;
    const int lid = tid & 31;
    const int qrow = tid >> 2;      // 0..127: row for prefetch
    const int qq   = tid & 3;       // quarter within row

    const float LOG2E = 1.4426950408889634f;
    float2* kk12 = reinterpret_cast<float2*>(smem + SMEM_KK);
    float*  wcs  = reinterpret_cast<float*>(smem + SMEM_WS);
    float*  x2s  = reinterpret_cast<float*>(smem + SMEM_X2);   // [2][128]
    float*  part = reinterpret_cast<float*>(smem + SMEM_PART); // [2][128]

    // ---- one-time: centres -> bf16 SW128 smem, per-centre constants ----
    for (int c = tid; c < CDIM; c += NTHREADS) {
        const float4* cr = reinterpret_cast<const float4*>(centres + c * DDIM);
        float c2 = 0.f;
#pragma unroll
        for (int j = 0; j < 8; j++) {
            float4 v0 = cr[2 * j];
            float4 v1 = cr[2 * j + 1];
            c2 += v0.x * v0.x + v0.y * v0.y + v0.z * v0.z + v0.w * v0.w
                + v1.x * v1.x + v1.y * v1.y + v1.z * v1.z + v1.w * v1.w;
            uint4 pk;
            pk.x = pack2(v0.x, v0.y); pk.y = pack2(v0.z, v0.w);
            pk.z = pack2(v1.x, v1.y); pk.w = pack2(v1.z, v1.w);
            STS128(sbase + SMEM_B + swz((uint32_t)(c * ROW_BYTES + j * 16)), pk);
        }
        float s = sigmas[c];
        float s2 = s * s;
        kk12[c] = make_float2(2.f * s2 * LOG2E, -s2 * c2 * LOG2E);
        wcs[c] = W[c];
    }
    if (tid < 2 * M_TILE) part[tid] = 0.f;
    __syncthreads();

    // ---- one-time: B fragments -> registers (warp owns cols wid*32..+31) ----
    uint32_t breg[4][4][2];
#pragma unroll
    for (int nf = 0; nf < 4; nf++) {
#pragma unroll
        for (int k = 0; k < 4; k++) {
            int c = wid * 32 + nf * 8 + (lid >> 2);
            uint32_t byte0 = (uint32_t)(c * ROW_BYTES) + (uint32_t)((k * 16 + (lid & 3) * 2) * 2);
            breg[nf][k][0] = lds32(sbase + SMEM_B + swz(byte0));
            breg[nf][k][1] = lds32(sbase + SMEM_B + swz(byte0 + 16));
        }
    }

    // ---- one-time: per-lane screen thresholds t_c = (T - kk)/k1 ----
    float tv[4][2];
#pragma unroll
    for (int nf = 0; nf < 4; nf++) {
#pragma unroll
        for (int j = 0; j < 2; j++) {
            int c = wid * 32 + nf * 8 + (lid & 3) * 2 + j;
            float2 kv = kk12[c];
            tv[nf][j] = (SCREEN_T - kv.y) / kv.x;
        }
    }
    const float bval = *bptr;

    // ---- prologue: all 512 threads stage first tile into buffer 0 ----
    int tile = blockIdx.x;
    {
        const float4* xr = reinterpret_cast<const float4*>(
            x + (size_t)(tile * M_TILE + qrow) * DDIM + qq * 16);
        float4 v0 = xr[0], v1 = xr[1], v2 = xr[2], v3 = xr[3];
        float x2 = v0.x*v0.x + v0.y*v0.y + v0.z*v0.z + v0.w*v0.w
                 + v1.x*v1.x + v1.y*v1.y + v1.z*v1.z + v1.w*v1.w
                 + v2.x*v2.x + v2.y*v2.y + v2.z*v2.z + v2.w*v2.w
                 + v3.x*v3.x + v3.y*v3.y + v3.z*v3.z + v3.w*v3.w;
        uint4 pk0, pk1;
        pk0.x = pack2(v0.x, v0.y); pk0.y = pack2(v0.z, v0.w);
        pk0.z = pack2(v1.x, v1.y); pk0.w = pack2(v1.z, v1.w);
        pk1.x = pack2(v2.x, v2.y); pk1.y = pack2(v2.z, v2.w);
        pk1.z = pack2(v3.x, v3.y); pk1.w = pack2(v3.z, v3.w);
        uint32_t rb = (uint32_t)(qrow * ROW_BYTES + qq * 32);
        STS128(sbase + SMEM_A + swz(rb), pk0);
        STS128(sbase + SMEM_A + swz(rb + 16), pk1);
        x2 += __shfl_xor_sync(0xffffffffu, x2, 1);
        x2 += __shfl_xor_sync(0xffffffffu, x2, 2);
        if (qq == 0) x2s[qrow] = x2;
    }
    __syncthreads();

    int p = 0;
    int pending = -1;   // tile whose output sits in part[p^1]
    for (; tile < NTILES; tile += GRID) {
        const int next = tile + GRID;
        const uint32_t abase = sbase + SMEM_A + (uint32_t)(p * 16384);
        const float* x2cur = x2s + p * M_TILE;

        // ---- stage next tile into buffer p^1 (overlaps MMA issue below) ----
        if (next < NTILES) {
            const float4* xr = reinterpret_cast<const float4*>(
                x + (size_t)(next * M_TILE + qrow) * DDIM + qq * 16);
            float4 v0 = xr[0], v1 = xr[1], v2 = xr[2], v3 = xr[3];
            float x2 = v0.x*v0.x + v0.y*v0.y + v0.z*v0.z + v0.w*v0.w
                     + v1.x*v1.x + v1.y*v1.y + v1.z*v1.z + v1.w*v1.w
                     + v2.x*v2.x + v2.y*v2.y + v2.z*v2.z + v2.w*v2.w
                     + v3.x*v3.x + v3.y*v3.y + v3.z*v3.z + v3.w*v3.w;
            uint4 pk0, pk1;
            pk0.x = pack2(v0.x, v0.y); pk0.y = pack2(v0.z, v0.w);
            pk0.z = pack2(v1.x, v1.y); pk0.w = pack2(v1.z, v1.w);
            pk1.x = pack2(v2.x, v2.y); pk1.y = pack2(v2.z, v2.w);
            pk1.z = pack2(v3.x, v3.y); pk1.w = pack2(v3.z, v3.w);
            uint32_t rb = (uint32_t)(qrow * ROW_BYTES + qq * 32);
            uint32_t nbase = sbase + SMEM_A + (uint32_t)((p ^ 1) * 16384);
            STS128(nbase + swz(rb), pk0);
            STS128(nbase + swz(rb + 16), pk1);
            x2 += __shfl_xor_sync(0xffffffffu, x2, 1);
            x2 += __shfl_xor_sync(0xffffffffu, x2, 2);
            if (qq == 0) x2s[(p ^ 1) * M_TILE + qrow] = x2;
        }

        // ---- store pending tile's output from part[p^1]; re-zero it ----
        if (pending >= 0 && tid < M_TILE) {
            out[pending * M_TILE + tid] = bval + part[(p ^ 1) * M_TILE + tid];
            part[(p ^ 1) * M_TILE + tid] = 0.f;
        }

        // ---- compute current tile: 8 m-fragments ----
#pragma unroll 1
        for (int mf = 0; mf < 8; mf++) {
            uint32_t a[4][4];
            const uint32_t arow = (uint32_t)(mf * 16 + (lid & 15));
#pragma unroll
            for (int k = 0; k < 4; k++) {
                uint32_t kbyte = (uint32_t)(k * 32 + ((lid >> 4) * 16));
                LDMATRIX_X4(a[k][0], a[k][1], a[k][2], a[k][3],
                            abase + swz(arow * ROW_BYTES + kbyte));
            }

            float acc[4][4];
#pragma unroll
            for (int nf = 0; nf < 4; nf++) {
                acc[nf][0] = 0.f; acc[nf][1] = 0.f; acc[nf][2] = 0.f; acc[nf][3] = 0.f;
            }
#pragma unroll
            for (int k = 0; k < 4; k++) {
#pragma unroll
                for (int nf = 0; nf < 4; nf++) {
                    MMA16816(acc[nf][0], acc[nf][1], acc[nf][2], acc[nf][3],
                             a[k][0], a[k][1], a[k][2], a[k][3],
                             breg[nf][k][0], breg[nf][k][1]);
                }
            }

            // cheap screen: any e > T ?  (dot - t > 0.5*x2)
            const int r0 = mf * 16 + (lid >> 2);
            const int r1 = r0 + 8;
            const float hx20 = 0.5f * x2cur[r0];
            const float hx21 = 0.5f * x2cur[r1];
            float m0 = fmaxf(acc[0][0] - tv[0][0], acc[0][1] - tv[0][1]);
            float m1 = fmaxf(acc[0][2] - tv[0][0], acc[0][3] - tv[0][1]);
#pragma unroll
            for (int nf = 1; nf < 4; nf++) {
                m0 = fmaxf(m0, fmaxf(acc[nf][0] - tv[nf][0], acc[nf][1] - tv[nf][1]));
                m1 = fmaxf(m1, fmaxf(acc[nf][2] - tv[nf][0], acc[nf][3] - tv[nf][1]));
            }
            bool hit = fmaxf(m0 - hx20, m1 - hx21) > 0.f;
            if (__any_sync(0xffffffffu, hit)) {   // ~never taken
#pragma unroll
                for (int nf = 0; nf < 4; nf++) {
#pragma unroll
                    for (int j = 0; j < 2; j++) {
                        int c = wid * 32 + nf * 8 + (lid & 3) * 2 + j;
                        float2 kv = kk12[c];
                        float wc = wcs[c];
                        float e0 = fmaf(kv.x, acc[nf][j]     - hx20, kv.y);
                        float e1 = fmaf(kv.x, acc[nf][2 + j] - hx21, kv.y);
                        if (e0 > SCREEN_T) atomicAdd(part + p * M_TILE + r0, ex2f(fminf(e0, 0.f)) * wc);
                        if (e1 > SCREEN_T) atomicAdd(part + p * M_TILE + r1, ex2f(fminf(e1, 0.f)) * wc);
                    }
                }
            }
        }

        __syncthreads();   // atomics done, next buffer staged, pending stored
        pending = tile;
        p ^= 1;
    }

    // ---- flush last tile's output (atomics completed at final barrier) ----
    if (pending >= 0 && tid < M_TILE) {
        out[pending * M_TILE + tid] = bval + part[(p ^ 1) * M_TILE + tid];
    }
}

extern "C" void kernel_launch(void* const* d_in, const int* in_sizes, int n_in,
                              void* d_out, int out_size) {
    const float* x       = (const float*)d_in[0];
    const float* centres = (const float*)d_in[1];
    const float* sigmas  = (const float*)d_in[2];
    const float* W       = (const float*)d_in[3];
    const float* b       = (const float*)d_in[4];
    float* out = (float*)d_out;

    cudaFuncSetAttribute(rbfn_kernel, cudaFuncAttributeMaxDynamicSharedMemorySize, SMEM_TOTAL);
    rbfn_kernel<<<GRID, NTHREADS, SMEM_TOTAL>>>(x, centres, sigmas, W, b, out);
}